// round 7
// baseline (speedup 1.0000x reference)
#include <cuda_runtime.h>

#define NDET    8192
#define ROW     85
#define IMG     640
#define CAP     256          // fast-path capacity (V ~ 77 expected)
#define W32     8            // 256/32 words per suppression row
#define NBLK    256
#define NTHR    1024

// Global scratch (allocation-free rule). g_cnt/g_done: zero at module load,
// reset by the last block every launch -> deterministic across graph replays.
__device__ int    g_cnt  = 0;
__device__ int    g_done = 0;
__device__ float  c_conf[NDET];
__device__ float4 c_box[NDET];
__device__ int    c_idx[NDET];
// slow-path (V > CAP) scratch only:
__device__ float  s_conf[NDET];
__device__ float4 s_box[NDET];

// ---------------------------------------------------------------------------
// Fused kernel: 256 blocks x 1024 threads (single wave, <=2 blocks/SM).
// Phase A (all blocks): zero out slice; one warp per detection decodes row,
//   warp max-reduce over class scores, validity, clamped xyxy; valid dets
//   compacted via global atomicAdd.
// Phase B (last finished block only, via threadfence+done counter):
//   rank sort (stable), ballot-built suppression bitmatrix, warp-0 branchless
//   greedy, scatter. Slow path for V > CAP.
// ---------------------------------------------------------------------------
__global__ void __launch_bounds__(NTHR) yolo_fused(const float* __restrict__ x,
                                                   float* __restrict__ out) {
    const int t    = threadIdx.x;
    const int lane = t & 31;
    const int wid  = t >> 5;

    __shared__ float sx1[CAP], sy1[CAP], sx2[CAP], sy2[CAP], scf[CAP];
    __shared__ unsigned long long skey[CAP];
    __shared__ unsigned int sup[CAP * W32];     // 8 KB (also slow-path keep[])
    __shared__ unsigned int keepw[W32];
    __shared__ int sh_last;

    // ================= Phase A: prep =================
    int gtid = blockIdx.x * NTHR + t;
    if (gtid < NDET * 5) out[gtid] = 0.0f;      // boxes (4*N) + scores (N)

    int det = blockIdx.x * 32 + wid;            // one warp per detection
    {
        const float* row = x + (long)det * ROW;
        float v0 = row[lane];
        float v1 = row[lane + 32];
        float v2 = (lane < 21) ? row[lane + 64] : -1e30f;

        // max over class scores at positions 6..84 (class ids 1..79)
        float m = (lane >= 6) ? v0 : -1e30f;
        m = fmaxf(m, v1);
        m = fmaxf(m, v2);
        #pragma unroll
        for (int o = 16; o; o >>= 1)
            m = fmaxf(m, __shfl_xor_sync(0xffffffffu, m, o));

        float b0   = __shfl_sync(0xffffffffu, v0, 0);
        float b1   = __shfl_sync(0xffffffffu, v0, 1);
        float b2   = __shfl_sync(0xffffffffu, v0, 2);
        float b3   = __shfl_sync(0xffffffffu, v0, 3);
        float conf = __shfl_sync(0xffffffffu, v0, 4);
        float cls0 = __shfl_sync(0xffffffffu, v0, 5);

        if (lane == 0) {
            float cx = b0 * 640.0f, cy = b1 * 640.0f;
            float w  = b2 * 640.0f, h  = b3 * 640.0f;
            // argmax==0  <=>  no later class strictly greater than cls0
            if ((conf > 0.25f) && (cls0 >= m) && ((w > 0.0f) || (h > 0.0f))) {
                float hw = truncf(w * 0.5f);
                float hh = truncf(h * 0.5f);
                int x1 = (int)(cx - hw);
                int y1 = (int)(cy - hh);
                int x2 = (int)(cx + hw);
                int y2 = (int)(cy + hh);
                x1 = x1 > 0 ? x1 : 0;
                y1 = y1 > 0 ? y1 : 0;
                x2 = x2 < IMG ? x2 : IMG;
                y2 = y2 < IMG ? y2 : IMG;
                int slot = atomicAdd(&g_cnt, 1);
                c_conf[slot] = conf;
                c_idx[slot]  = det;
                c_box[slot]  = make_float4((float)x1, (float)y1,
                                           (float)x2, (float)y2);
            }
        }
    }

    // ---- completion handshake: last finished block runs NMS ----
    __syncthreads();            // all warps in block done (incl. out zeroing)
    __threadfence();            // block's global writes visible
    if (t == 0) {
        int prev = atomicAdd(&g_done, 1);
        sh_last = (prev == NBLK - 1);
    }
    __syncthreads();
    if (!sh_last) return;
    __threadfence();            // acquire side: see all blocks' writes

    // ================= Phase B: NMS (single block) =================
    const int V = g_cnt;

    if (V <= CAP) {
        // ---- load + key build ----
        float mcf = 0, mx1 = 0, my1 = 0, mx2 = 0, my2 = 0;
        unsigned long long mykey = 0;
        if (t < V) {
            float4 b = c_box[t];
            mcf = c_conf[t];
            int idx = c_idx[t];
            mx1 = b.x; my1 = b.y; mx2 = b.z; my2 = b.w;
            mykey = ((unsigned long long)__float_as_uint(mcf) << 32)
                  | (unsigned int)(~idx);
            skey[t] = mykey;
        }
        __syncthreads();

        // ---- rank sort (stable: conf desc, original idx asc) ----
        if (t < V) {
            int r = 0;
            int j = 0;
            for (; j + 4 <= V; j += 4) {
                r += (skey[j]     > mykey);
                r += (skey[j + 1] > mykey);
                r += (skey[j + 2] > mykey);
                r += (skey[j + 3] > mykey);
            }
            for (; j < V; j++) r += (skey[j] > mykey);
            sx1[r] = mx1; sy1[r] = my1; sx2[r] = mx2; sy2[r] = my2; scf[r] = mcf;
        }
        __syncthreads();

        // ---- suppression matrix: warp per row, ballot per 32-j word ----
        const int nw = (V + 31) >> 5;
        for (int i = wid; i < V; i += 32) {
            float x1i = sx1[i], y1i = sy1[i], x2i = sx2[i], y2i = sy2[i];
            float areai = (x2i - x1i) * (y2i - y1i);   // exact in fp32
            for (int b = 0; b < nw; b++) {
                int j = (b << 5) + lane;
                bool s = false;
                if (j > i && j < V) {
                    float x1j = sx1[j], y1j = sy1[j];
                    float x2j = sx2[j], y2j = sy2[j];
                    float iw = fmaxf(fminf(x2i, x2j) - fmaxf(x1i, x1j), 0.0f);
                    float ih = fmaxf(fminf(y2i, y2j) - fmaxf(y1i, y1j), 0.0f);
                    float inter = iw * ih;
                    float areaj = (x2j - x1j) * (y2j - y1j);
                    float uni = areai + areaj - inter;
                    float iou = __fdiv_rn(inter, fmaxf(uni, 1e-9f)); // IEEE
                    s = iou > 0.45f;
                }
                unsigned int bits = __ballot_sync(0xffffffffu, s);
                if (lane == 0) sup[i * W32 + b] = bits;
            }
        }
        __syncthreads();

        // ---- warp-0 branchless greedy: keep word per lane ----
        if (wid == 0) {
            unsigned int kw = 0xFFFFFFFFu;   // lane w keeps bits [32w,32w+32)
            for (int i = 0; i < V; i++) {
                unsigned int row = (lane < nw) ? sup[i * W32 + lane] : 0u;
                unsigned int wi = __shfl_sync(0xffffffffu, kw, i >> 5);
                unsigned int alive = (wi >> (i & 31)) & 1u;
                kw &= ~(row & (0u - alive));
            }
            if (lane < W32) keepw[lane] = kw;
        }
        __syncthreads();

        // ---- scatter survivors (rest of out zeroed in Phase A) ----
        if (t < V && ((keepw[t >> 5] >> (t & 31)) & 1u)) {
            out[4 * t + 0] = sx1[t];
            out[4 * t + 1] = sy1[t];
            out[4 * t + 2] = sx2[t];
            out[4 * t + 3] = sy2[t];
            out[NDET * 4 + t] = scf[t];
        }
        if (t == 0) { g_cnt = 0; g_done = 0; }   // reset for next replay
    } else {
        // ============ SLOW PATH (V > CAP; global arrays) ============
        for (int i = t; i < V; i += NTHR) {
            float ci = c_conf[i];
            int  ii  = c_idx[i];
            int r = 0;
            for (int j = 0; j < V; j++) {
                float cj = c_conf[j];
                r += (cj > ci) || (cj == ci && c_idx[j] < ii);
            }
            s_conf[r] = ci;
            s_box[r]  = c_box[i];
        }
        __syncthreads();

        unsigned char* keep = (unsigned char*)&sup[0];   // 8KB == NDET bytes
        for (int i = t; i < NDET; i += NTHR) keep[i] = 1;
        __syncthreads();
        for (int i = 0; i + 1 < V; i++) {
            if (keep[i]) {
                float4 bi = s_box[i];
                float areai = (bi.z - bi.x) * (bi.w - bi.y);
                for (int j = i + 1 + t; j < V; j += NTHR) {
                    if (keep[j]) {
                        float4 bj = s_box[j];
                        float iw = fmaxf(fminf(bi.z, bj.z) - fmaxf(bi.x, bj.x), 0.0f);
                        float ih = fmaxf(fminf(bi.w, bj.w) - fmaxf(bi.y, bj.y), 0.0f);
                        float inter = iw * ih;
                        float areaj = (bj.z - bj.x) * (bj.w - bj.y);
                        float uni = areai + areaj - inter;
                        float iou = __fdiv_rn(inter, fmaxf(uni, 1e-9f));
                        if (iou > 0.45f) keep[j] = 0;
                    }
                }
            }
            __syncthreads();
        }
        for (int i = t; i < V; i += NTHR) {
            if (keep[i]) {
                float4 b = s_box[i];
                out[4 * i + 0] = b.x;
                out[4 * i + 1] = b.y;
                out[4 * i + 2] = b.z;
                out[4 * i + 3] = b.w;
                out[NDET * 4 + i] = s_conf[i];
            }
        }
        if (t == 0) { g_cnt = 0; g_done = 0; }
    }
}

extern "C" void kernel_launch(void* const* d_in, const int* in_sizes, int n_in,
                              void* d_out, int out_size) {
    const float* x = (const float*)d_in[0];   // (1, 8192, 85) fp32
    float* out = (float*)d_out;               // 8192*4 boxes then 8192 scores
    yolo_fused<<<NBLK, NTHR>>>(x, out);
}

// round 8
// speedup vs baseline: 1.0781x; 1.0781x over previous
#include <cuda_runtime.h>

#define NDET    8192
#define ROW     85
#define IMG     640
#define CAP     128          // fast-path capacity (V ~ 77 expected, 5.8 sigma)
#define W32     4            // 128/32 words per suppression row
#define NBLK    128
#define NTHR    1024

// Global scratch (allocation-free rule). g_cnt/g_done: zero at module load,
// reset by the NMS block every launch -> deterministic across graph replays.
__device__ int    g_cnt  = 0;
__device__ int    g_done = 0;
__device__ float  c_conf[NDET];
__device__ float4 c_box[NDET];
__device__ int    c_idx[NDET];
// slow-path (V > CAP) scratch only:
__device__ float  s_conf[NDET];
__device__ float4 s_box[NDET];

// ---------------------------------------------------------------------------
// Fused kernel: 128 blocks x 1024 threads = 1 block/SM, one balanced wave.
// Phase A: zero out slice; each warp decodes 2 detections (warp max-reduce
//   over class scores, validity, clamped xyxy); valid dets compacted via
//   global atomicAdd.
// Phase B (last finished block): rank sort, ballot suppression bitmatrix,
//   single-thread register greedy (no shfl in carry chain), scatter.
// ---------------------------------------------------------------------------
__global__ void __launch_bounds__(NTHR) yolo_fused(const float* __restrict__ x,
                                                   float* __restrict__ out) {
    const int t    = threadIdx.x;
    const int lane = t & 31;
    const int wid  = t >> 5;

    __shared__ float sx1[CAP], sy1[CAP], sx2[CAP], sy2[CAP], scf[CAP];
    __shared__ unsigned long long skey[CAP];
    __shared__ unsigned int sup[2048];   // fast: CAP*W32=512 used; slow: 8KB keep[]
    __shared__ unsigned int keepw[W32];
    __shared__ int sh_last;

    // ================= Phase A: prep (2 detections per warp) =================
    int gtid = blockIdx.x * NTHR + t;
    if (gtid < NDET * 5) out[gtid] = 0.0f;      // boxes (4*N) + scores (N)

    #pragma unroll
    for (int pass = 0; pass < 2; pass++) {
        int det = blockIdx.x * 64 + pass * 32 + wid;
        const float* row = x + (long)det * ROW;
        float v0 = row[lane];
        float v1 = row[lane + 32];
        float v2 = (lane < 21) ? row[lane + 64] : -1e30f;

        // max over class scores at positions 6..84 (class ids 1..79)
        float m = (lane >= 6) ? v0 : -1e30f;
        m = fmaxf(m, v1);
        m = fmaxf(m, v2);
        #pragma unroll
        for (int o = 16; o; o >>= 1)
            m = fmaxf(m, __shfl_xor_sync(0xffffffffu, m, o));

        float b0   = __shfl_sync(0xffffffffu, v0, 0);
        float b1   = __shfl_sync(0xffffffffu, v0, 1);
        float b2   = __shfl_sync(0xffffffffu, v0, 2);
        float b3   = __shfl_sync(0xffffffffu, v0, 3);
        float conf = __shfl_sync(0xffffffffu, v0, 4);
        float cls0 = __shfl_sync(0xffffffffu, v0, 5);

        if (lane == 0) {
            float cx = b0 * 640.0f, cy = b1 * 640.0f;
            float w  = b2 * 640.0f, h  = b3 * 640.0f;
            // argmax==0  <=>  no later class strictly greater than cls0
            if ((conf > 0.25f) && (cls0 >= m) && ((w > 0.0f) || (h > 0.0f))) {
                float hw = truncf(w * 0.5f);
                float hh = truncf(h * 0.5f);
                int x1 = (int)(cx - hw);
                int y1 = (int)(cy - hh);
                int x2 = (int)(cx + hw);
                int y2 = (int)(cy + hh);
                x1 = x1 > 0 ? x1 : 0;
                y1 = y1 > 0 ? y1 : 0;
                x2 = x2 < IMG ? x2 : IMG;
                y2 = y2 < IMG ? y2 : IMG;
                int slot = atomicAdd(&g_cnt, 1);
                c_conf[slot] = conf;
                c_idx[slot]  = det;
                c_box[slot]  = make_float4((float)x1, (float)y1,
                                           (float)x2, (float)y2);
            }
        }
    }

    // ---- completion handshake: last finished block runs NMS ----
    __syncthreads();            // block done (incl. out zeroing)
    __threadfence();            // block's global writes visible
    if (t == 0) {
        int prev = atomicAdd(&g_done, 1);
        sh_last = (prev == NBLK - 1);
    }
    __syncthreads();
    if (!sh_last) return;
    __threadfence();            // acquire: see all blocks' writes

    // ================= Phase B: NMS (single block) =================
    // Issue V-count and candidate loads concurrently (one L2 round trip).
    // Lanes t >= V read stale-but-deterministically-masked data: every use
    // below is guarded by t < V.
    float mcf = 0, mx1 = 0, my1 = 0, mx2 = 0, my2 = 0;
    int   midx = 0;
    if (t < CAP) {
        float4 b = c_box[t];
        mcf  = c_conf[t];
        midx = c_idx[t];
        mx1 = b.x; my1 = b.y; mx2 = b.z; my2 = b.w;
    }
    const int V = g_cnt;

    if (V <= CAP) {
        unsigned long long mykey = 0;
        if (t < V) {
            mykey = ((unsigned long long)__float_as_uint(mcf) << 32)
                  | (unsigned int)(~midx);
            skey[t] = mykey;
        }
        __syncthreads();

        // ---- rank sort (stable: conf desc, original idx asc) ----
        if (t < V) {
            int r = 0;
            int j = 0;
            for (; j + 4 <= V; j += 4) {
                r += (skey[j]     > mykey);
                r += (skey[j + 1] > mykey);
                r += (skey[j + 2] > mykey);
                r += (skey[j + 3] > mykey);
            }
            for (; j < V; j++) r += (skey[j] > mykey);
            sx1[r] = mx1; sy1[r] = my1; sx2[r] = mx2; sy2[r] = my2; scf[r] = mcf;
        }
        __syncthreads();

        // ---- suppression matrix: warp per row, ballot per 32-j word ----
        const int nw = (V + 31) >> 5;
        for (int i = wid; i < V; i += 32) {
            float x1i = sx1[i], y1i = sy1[i], x2i = sx2[i], y2i = sy2[i];
            float areai = (x2i - x1i) * (y2i - y1i);   // exact in fp32
            for (int b = 0; b < nw; b++) {
                int j = (b << 5) + lane;
                bool s = false;
                if (j > i && j < V) {
                    float x1j = sx1[j], y1j = sy1[j];
                    float x2j = sx2[j], y2j = sy2[j];
                    float iw = fmaxf(fminf(x2i, x2j) - fmaxf(x1i, x1j), 0.0f);
                    float ih = fmaxf(fminf(y2i, y2j) - fmaxf(y1i, y1j), 0.0f);
                    float inter = iw * ih;
                    float areaj = (x2j - x1j) * (y2j - y1j);
                    float uni = areai + areaj - inter;
                    float iou = __fdiv_rn(inter, fmaxf(uni, 1e-9f)); // IEEE
                    s = iou > 0.45f;
                }
                unsigned int bits = __ballot_sync(0xffffffffu, s);
                if (lane == 0) sup[i * W32 + b] = bits;
            }
        }
        __syncthreads();

        // ---- single-thread greedy: keep state in 4 registers, ALU chain ----
        if (t == 0) {
            unsigned int kw[W32];
            #pragma unroll
            for (int w = 0; w < W32; w++) kw[w] = 0xFFFFFFFFu;
            #pragma unroll
            for (int w = 0; w < W32; w++) {          // unrolled: kw[] in regs
                int rem = V - (w << 5);
                int bmax = rem < 32 ? rem : 32;
                for (int b = 0; b < bmax; b++) {
                    int i = (w << 5) + b;
                    unsigned int msk = 0u - ((kw[w] >> b) & 1u);
                    // row i has bits only for j > i; earlier words are zero
                    kw[0] &= ~(sup[i * W32 + 0] & msk);
                    kw[1] &= ~(sup[i * W32 + 1] & msk);
                    kw[2] &= ~(sup[i * W32 + 2] & msk);
                    kw[3] &= ~(sup[i * W32 + 3] & msk);
                }
            }
            #pragma unroll
            for (int w = 0; w < W32; w++) keepw[w] = kw[w];
        }
        __syncthreads();

        // ---- scatter survivors (rest of out zeroed in Phase A) ----
        if (t < V && ((keepw[t >> 5] >> (t & 31)) & 1u)) {
            out[4 * t + 0] = sx1[t];
            out[4 * t + 1] = sy1[t];
            out[4 * t + 2] = sx2[t];
            out[4 * t + 3] = sy2[t];
            out[NDET * 4 + t] = scf[t];
        }
        if (t == 0) { g_cnt = 0; g_done = 0; }   // reset for next replay
    } else {
        // ============ SLOW PATH (V > CAP; global arrays) ============
        for (int i = t; i < V; i += NTHR) {
            float ci = c_conf[i];
            int  ii  = c_idx[i];
            int r = 0;
            for (int j = 0; j < V; j++) {
                float cj = c_conf[j];
                r += (cj > ci) || (cj == ci && c_idx[j] < ii);
            }
            s_conf[r] = ci;
            s_box[r]  = c_box[i];
        }
        __syncthreads();

        unsigned char* keep = (unsigned char*)&sup[0];   // 8KB == NDET bytes
        for (int i = t; i < NDET; i += NTHR) keep[i] = 1;
        __syncthreads();
        for (int i = 0; i + 1 < V; i++) {
            if (keep[i]) {
                float4 bi = s_box[i];
                float areai = (bi.z - bi.x) * (bi.w - bi.y);
                for (int j = i + 1 + t; j < V; j += NTHR) {
                    if (keep[j]) {
                        float4 bj = s_box[j];
                        float iw = fmaxf(fminf(bi.z, bj.z) - fmaxf(bi.x, bj.x), 0.0f);
                        float ih = fmaxf(fminf(bi.w, bj.w) - fmaxf(bi.y, bj.y), 0.0f);
                        float inter = iw * ih;
                        float areaj = (bj.z - bj.x) * (bj.w - bj.y);
                        float uni = areai + areaj - inter;
                        float iou = __fdiv_rn(inter, fmaxf(uni, 1e-9f));
                        if (iou > 0.45f) keep[j] = 0;
                    }
                }
            }
            __syncthreads();
        }
        for (int i = t; i < V; i += NTHR) {
            if (keep[i]) {
                float4 b = s_box[i];
                out[4 * i + 0] = b.x;
                out[4 * i + 1] = b.y;
                out[4 * i + 2] = b.z;
                out[4 * i + 3] = b.w;
                out[NDET * 4 + i] = s_conf[i];
            }
        }
        if (t == 0) { g_cnt = 0; g_done = 0; }
    }
}

extern "C" void kernel_launch(void* const* d_in, const int* in_sizes, int n_in,
                              void* d_out, int out_size) {
    const float* x = (const float*)d_in[0];   // (1, 8192, 85) fp32
    float* out = (float*)d_out;               // 8192*4 boxes then 8192 scores
    yolo_fused<<<NBLK, NTHR>>>(x, out);
}